// round 9
// baseline (speedup 1.0000x reference)
#include <cuda_runtime.h>
#include <cstdint>

// Problem constants
#define BATCH 32
#define CIN   64
#define HID   384
#define RED   16
#define COUT  64
#define HS    56
#define HW    3136              // 56*56
#define NPIX  (BATCH*HW)        // 100352
#define KEXP  (CIN*9)           // 576

// Scratch (allocation-free: __device__ globals)
__device__ float g_h[BATCH*HID*HW];     // after expand conv + BN + SiLU
__device__ float g_d[BATCH*HID*HW];     // after depthwise + BN + SiLU
__device__ float g_pool[BATCH*HID];     // global average pool of g_d
__device__ float g_s[BATCH*HID];        // SE gate
__device__ float g_sc1[HID], g_sh1[HID];
__device__ float g_sc2[HID], g_sh2[HID];
__device__ float g_sc3[COUT], g_sh3[COUT];

__device__ __forceinline__ float silu_f(float v)    { return v / (1.f + __expf(-v)); }
__device__ __forceinline__ float sigmoid_f(float v) { return 1.f / (1.f + __expf(-v)); }

__device__ __forceinline__ uint32_t f32_to_tf32(float f) {
    uint32_t o;
    asm("cvt.rna.tf32.f32 %0, %1;" : "=r"(o) : "f"(f));
    return o;
}

// mma.sync m16n8k8 tf32: D[16x8] += A[16x8] * B[8x8]
__device__ __forceinline__ void mma_tf32(float* c, const uint32_t* a, const uint32_t* b) {
    asm volatile(
        "mma.sync.aligned.m16n8k8.row.col.f32.tf32.tf32.f32 "
        "{%0,%1,%2,%3}, {%4,%5,%6,%7}, {%8,%9}, {%0,%1,%2,%3};"
        : "+f"(c[0]), "+f"(c[1]), "+f"(c[2]), "+f"(c[3])
        : "r"(a[0]), "r"(a[1]), "r"(a[2]), "r"(a[3]), "r"(b[0]), "r"(b[1]));
}

// ---------------------------------------------------------------------------
// Kernel 0: fold BN params into per-channel scale/shift
// ---------------------------------------------------------------------------
__global__ void bn_prep_kernel(
    const float* __restrict__ g1, const float* __restrict__ b1,
    const float* __restrict__ m1, const float* __restrict__ v1,
    const float* __restrict__ g2, const float* __restrict__ b2,
    const float* __restrict__ m2, const float* __restrict__ v2,
    const float* __restrict__ g3, const float* __restrict__ b3,
    const float* __restrict__ m3, const float* __restrict__ v3)
{
    int t = threadIdx.x;
    if (t < HID) {
        float s1 = g1[t] * rsqrtf(v1[t] + 1e-5f);
        g_sc1[t] = s1; g_sh1[t] = b1[t] - m1[t] * s1;
        float s2 = g2[t] * rsqrtf(v2[t] + 1e-5f);
        g_sc2[t] = s2; g_sh2[t] = b2[t] - m2[t] * s2;
    }
    if (t < COUT) {
        float s3 = g3[t] * rsqrtf(v3[t] + 1e-5f);
        g_sc3[t] = s3; g_sh3[t] = b3[t] - m3[t] * s3;
    }
}

// ---------------------------------------------------------------------------
// Kernel 1: expand conv 3x3 (64->384) via tensor-core mma.sync (tf32),
//           fused BN1 + SiLU. (proven in round 7; unchanged)
// ---------------------------------------------------------------------------
#define PADK 136

__global__ __launch_bounds__(256, 2)
void expand_conv_mma_kernel(const float* __restrict__ x, const float* __restrict__ w)
{
    __shared__ float As[8][PADK];   // As[k][m] (tf32 bit patterns)
    __shared__ float Bs[8][PADK];   // Bs[k][n]

    const int tid = threadIdx.x;
    const int wid = tid >> 5;
    const int lid = tid & 31;
    const int g   = lid >> 2;       // 0..7
    const int t   = lid & 3;        // 0..3
    const int wm  = (wid >> 1) * 32;    // warp m-offset within 128
    const int wn  = (wid & 1) * 64;     // warp n-offset within 128
    const int m0  = blockIdx.y * 128;
    const int n0  = blockIdx.x * 128;

    const int kk = tid >> 5;               // 0..7
    const int n4 = (lid) << 2;             // 0..124
    int xoff[4], boh[4], bow[4];
#pragma unroll
    for (int j = 0; j < 4; j++) {
        int ncol = n0 + n4 + j;
        int b = ncol / HW;
        int p = ncol - b * HW;
        int oh = p / HS;
        int ow = p - oh * HS;
        boh[j] = oh; bow[j] = ow;
        xoff[j] = b * (CIN * HW) + oh * HS + ow;
    }

    const int am  = tid >> 1;              // 0..127
    const int ak4 = (tid & 1) * 4;         // 0 or 4
    const float* wrow = w + (size_t)(m0 + am) * KEXP + ak4;

    float acc[2][8][4];
#pragma unroll
    for (int i = 0; i < 2; i++)
#pragma unroll
        for (int j = 0; j < 8; j++)
#pragma unroll
            for (int q = 0; q < 4; q++) acc[i][j][q] = 0.f;

    float4 avp;
    float  bvp[4];
    auto fetch = [&](int k0) {
        avp = *reinterpret_cast<const float4*>(wrow + k0);
        int kq = k0 + kk;
        int ic = kq / 9;
        int r  = kq - ic * 9;
        int r3 = r / 3;
        int dh = r3 - 1;
        int dw = (r - r3 * 3) - 1;
        const float* xp = x + ic * HW + dh * HS + dw;
#pragma unroll
        for (int j = 0; j < 4; j++) {
            int ih = boh[j] + dh;
            int iw = bow[j] + dw;
            bool ok = ((unsigned)ih < (unsigned)HS) && ((unsigned)iw < (unsigned)HS);
            bvp[j] = ok ? __ldg(xp + xoff[j]) : 0.f;
        }
    };

    fetch(0);

    for (int k0 = 0; k0 < KEXP; k0 += 8) {
        As[ak4 + 0][am] = __uint_as_float(f32_to_tf32(avp.x));
        As[ak4 + 1][am] = __uint_as_float(f32_to_tf32(avp.y));
        As[ak4 + 2][am] = __uint_as_float(f32_to_tf32(avp.z));
        As[ak4 + 3][am] = __uint_as_float(f32_to_tf32(avp.w));
#pragma unroll
        for (int j = 0; j < 4; j++)
            Bs[kk][n4 + j] = __uint_as_float(f32_to_tf32(bvp[j]));
        __syncthreads();

        if (k0 + 8 < KEXP) fetch(k0 + 8);

        uint32_t afr[2][4];
#pragma unroll
        for (int fm = 0; fm < 2; fm++) {
            int mb = wm + fm * 16;
            afr[fm][0] = __float_as_uint(As[t][mb + g]);
            afr[fm][1] = __float_as_uint(As[t][mb + g + 8]);
            afr[fm][2] = __float_as_uint(As[t + 4][mb + g]);
            afr[fm][3] = __float_as_uint(As[t + 4][mb + g + 8]);
        }
#pragma unroll
        for (int fn = 0; fn < 8; fn++) {
            uint32_t bfr[2];
            int nb = wn + fn * 8;
            bfr[0] = __float_as_uint(Bs[t][nb + g]);
            bfr[1] = __float_as_uint(Bs[t + 4][nb + g]);
            mma_tf32(acc[0][fn], afr[0], bfr);
            mma_tf32(acc[1][fn], afr[1], bfr);
        }
        __syncthreads();
    }

#pragma unroll
    for (int fm = 0; fm < 2; fm++) {
#pragma unroll
        for (int half = 0; half < 2; half++) {
            int oc = m0 + wm + fm * 16 + g + half * 8;
            float sc = g_sc1[oc], sh = g_sh1[oc];
#pragma unroll
            for (int fn = 0; fn < 8; fn++) {
#pragma unroll
                for (int e = 0; e < 2; e++) {
                    int ncol = n0 + wn + fn * 8 + 2 * t + e;
                    int b = ncol / HW;
                    int p = ncol - b * HW;
                    float v = fmaf(acc[fm][fn][half * 2 + e], sc, sh);
                    g_h[((size_t)b * HID + oc) * HW + p] = silu_f(v);
                }
            }
        }
    }
}

// ---------------------------------------------------------------------------
// Kernel 2: depthwise 3x3 + BN2 + SiLU, fused global-average-pool partial
// ---------------------------------------------------------------------------
__global__ __launch_bounds__(256)
void dw_conv_kernel(const float* __restrict__ wdw)
{
    const int bc = blockIdx.x;            // b*HID + c
    const int c  = bc % HID;
    const float* __restrict__ hp = g_h + (size_t)bc * HW;
    float* __restrict__ dp = g_d + (size_t)bc * HW;

    float w[9];
#pragma unroll
    for (int i = 0; i < 9; i++) w[i] = wdw[c * 9 + i];
    const float sc = g_sc2[c], sh = g_sh2[c];

    float lsum = 0.f;
    for (int p = threadIdx.x; p < HW; p += 256) {
        int oh = p / HS;
        int ow = p - oh * HS;
        float acc = 0.f;
#pragma unroll
        for (int kh = 0; kh < 3; kh++) {
            int ih = oh + kh - 1;
            if ((unsigned)ih < (unsigned)HS) {
#pragma unroll
                for (int kw = 0; kw < 3; kw++) {
                    int iw = ow + kw - 1;
                    if ((unsigned)iw < (unsigned)HS)
                        acc = fmaf(w[kh * 3 + kw], hp[ih * HS + iw], acc);
                }
            }
        }
        float v = silu_f(fmaf(acc, sc, sh));
        dp[p] = v;
        lsum += v;
    }

    __shared__ float red[256];
    red[threadIdx.x] = lsum;
    __syncthreads();
#pragma unroll
    for (int s = 128; s > 0; s >>= 1) {
        if (threadIdx.x < s) red[threadIdx.x] += red[threadIdx.x + s];
        __syncthreads();
    }
    if (threadIdx.x == 0) g_pool[bc] = red[0] * (1.f / (float)HW);
}

// ---------------------------------------------------------------------------
// Kernel 3: squeeze-excitation. Warp-parallel first FC (12 warps, shfl reduce)
// ---------------------------------------------------------------------------
__global__ void se_kernel(const float* __restrict__ w1, const float* __restrict__ w2)
{
    const int b = blockIdx.x;
    const int t = threadIdx.x;            // 0..383
    const int wid = t >> 5;               // 0..11
    const int lid = t & 31;
    __shared__ float pool[HID];
    __shared__ float s1[RED];

    pool[t] = g_pool[b * HID + t];
    __syncthreads();

    // first FC: each warp handles outputs r = wid, wid+12 (r < 16)
    for (int r = wid; r < RED; r += 12) {
        const float* wr = w1 + r * HID;
        float part = 0.f;
#pragma unroll
        for (int c = lid; c < HID; c += 32)
            part = fmaf(wr[c], pool[c], part);
#pragma unroll
        for (int off = 16; off > 0; off >>= 1)
            part += __shfl_xor_sync(0xFFFFFFFF, part, off);
        if (lid == 0) s1[r] = silu_f(part);
    }
    __syncthreads();

    float acc = 0.f;
#pragma unroll
    for (int r = 0; r < RED; r++)
        acc = fmaf(w2[t * RED + r], s1[r], acc);
    g_s[b * HID + t] = sigmoid_f(acc);
}

// ---------------------------------------------------------------------------
// Kernel 4: pointwise 1x1 (384->64) via tensor-core mma.sync (tf32),
//           SE gate folded into B, fused BN3 + residual add.
//   GEMM: C[64, 100352] = Wpw[64, 384] @ (d*s)[384, 100352]
//   Block tile M=64 x N=128, 8 warps (2x4), warp tile 32x32, K-step 8.
// ---------------------------------------------------------------------------
#define PADM 72
#define PADN 136

__global__ __launch_bounds__(256, 2)
void pw_conv_mma_kernel(const float* __restrict__ wpw, const float* __restrict__ x,
                        float* __restrict__ out)
{
    __shared__ float As[8][PADM];   // As[k][m]
    __shared__ float Bs[8][PADN];   // Bs[k][n]

    const int tid = threadIdx.x;
    const int wid = tid >> 5;
    const int lid = tid & 31;
    const int g   = lid >> 2;
    const int t   = lid & 3;
    const int wm  = (wid & 1) * 32;       // warp m-offset (0 or 32)
    const int wn  = (wid >> 1) * 32;      // warp n-offset (0,32,64,96)
    const int n0  = blockIdx.x * 128;

    // A loader: thread -> (row am 0..63, 2 consecutive k)
    const int am  = tid >> 2;             // 0..63
    const int ak2 = (tid & 3) * 2;        // 0,2,4,6
    const float* wrow = wpw + (size_t)am * HID + ak2;

    // B loader: thread -> (k-row kk 0..7, 4 consecutive n)
    const int kk = tid >> 5;
    const int n4 = lid << 2;
    int jb[4], jp[4];
#pragma unroll
    for (int j = 0; j < 4; j++) {
        int ncol = n0 + n4 + j;
        int b = ncol / HW;
        jb[j] = b;
        jp[j] = ncol - b * HW;
    }

    float acc[2][4][4];
#pragma unroll
    for (int i = 0; i < 2; i++)
#pragma unroll
        for (int j = 0; j < 4; j++)
#pragma unroll
            for (int q = 0; q < 4; q++) acc[i][j][q] = 0.f;

    float2 avp;
    float  bvp[4];
    auto fetch = [&](int k0) {
        avp = *reinterpret_cast<const float2*>(wrow + k0);
        int c = k0 + kk;
#pragma unroll
        for (int j = 0; j < 4; j++) {
            int bg = jb[j] * HID + c;
            bvp[j] = g_d[(size_t)bg * HW + jp[j]] * g_s[bg];
        }
    };

    fetch(0);

    for (int k0 = 0; k0 < HID; k0 += 8) {
        As[ak2 + 0][am] = __uint_as_float(f32_to_tf32(avp.x));
        As[ak2 + 1][am] = __uint_as_float(f32_to_tf32(avp.y));
#pragma unroll
        for (int j = 0; j < 4; j++)
            Bs[kk][n4 + j] = __uint_as_float(f32_to_tf32(bvp[j]));
        __syncthreads();

        if (k0 + 8 < HID) fetch(k0 + 8);

        uint32_t afr[2][4];
#pragma unroll
        for (int fm = 0; fm < 2; fm++) {
            int mb = wm + fm * 16;
            afr[fm][0] = __float_as_uint(As[t][mb + g]);
            afr[fm][1] = __float_as_uint(As[t][mb + g + 8]);
            afr[fm][2] = __float_as_uint(As[t + 4][mb + g]);
            afr[fm][3] = __float_as_uint(As[t + 4][mb + g + 8]);
        }
#pragma unroll
        for (int fn = 0; fn < 4; fn++) {
            uint32_t bfr[2];
            int nb = wn + fn * 8;
            bfr[0] = __float_as_uint(Bs[t][nb + g]);
            bfr[1] = __float_as_uint(Bs[t + 4][nb + g]);
            mma_tf32(acc[0][fn], afr[0], bfr);
            mma_tf32(acc[1][fn], afr[1], bfr);
        }
        __syncthreads();
    }

    // epilogue: BN3 + residual add
#pragma unroll
    for (int fm = 0; fm < 2; fm++) {
#pragma unroll
        for (int half = 0; half < 2; half++) {
            int oc = wm + fm * 16 + g + half * 8;
            float sc = g_sc3[oc], sh = g_sh3[oc];
#pragma unroll
            for (int fn = 0; fn < 4; fn++) {
#pragma unroll
                for (int e = 0; e < 2; e++) {
                    int ncol = n0 + wn + fn * 8 + 2 * t + e;
                    int b = ncol / HW;
                    int p = ncol - b * HW;
                    int idx = (b * COUT + oc) * HW + p;
                    out[idx] = fmaf(acc[fm][fn][half * 2 + e], sc, sh) + x[idx];
                }
            }
        }
    }
}

// ---------------------------------------------------------------------------
// Launch
// ---------------------------------------------------------------------------
extern "C" void kernel_launch(void* const* d_in, const int* in_sizes, int n_in,
                              void* d_out, int out_size)
{
    const float* x     = (const float*)d_in[0];
    const float* w_exp = (const float*)d_in[1];
    const float* g1 = (const float*)d_in[2];
    const float* b1 = (const float*)d_in[3];
    const float* m1 = (const float*)d_in[4];
    const float* v1 = (const float*)d_in[5];
    const float* w_dw = (const float*)d_in[6];
    const float* g2 = (const float*)d_in[7];
    const float* b2 = (const float*)d_in[8];
    const float* m2 = (const float*)d_in[9];
    const float* v2 = (const float*)d_in[10];
    const float* w_se1 = (const float*)d_in[11];
    const float* w_se2 = (const float*)d_in[12];
    const float* w_pw  = (const float*)d_in[13];
    const float* g3 = (const float*)d_in[14];
    const float* b3 = (const float*)d_in[15];
    const float* m3 = (const float*)d_in[16];
    const float* v3 = (const float*)d_in[17];
    float* out = (float*)d_out;

    bn_prep_kernel<<<1, HID>>>(g1, b1, m1, v1, g2, b2, m2, v2, g3, b3, m3, v3);
    expand_conv_mma_kernel<<<dim3(NPIX / 128, HID / 128), 256>>>(x, w_exp);
    dw_conv_kernel<<<BATCH * HID, 256>>>(w_dw);
    se_kernel<<<BATCH, HID>>>(w_se1, w_se2);
    pw_conv_mma_kernel<<<NPIX / 128, 256>>>(w_pw, x, out);
}

// round 10
// speedup vs baseline: 1.5014x; 1.5014x over previous
#include <cuda_runtime.h>
#include <cstdint>

// Problem constants
#define BATCH 32
#define CIN   64
#define HID   384
#define RED   16
#define COUT  64
#define HS    56
#define HW    3136              // 56*56
#define NPIX  (BATCH*HW)        // 100352
#define KEXP  (CIN*9)           // 576

// Scratch (allocation-free: __device__ globals)
__device__ float g_h[BATCH*HID*HW];     // after expand conv + BN + SiLU
__device__ float g_d[BATCH*HID*HW];     // after depthwise + BN + SiLU
__device__ float g_pool[BATCH*HID];     // global average pool of g_d
__device__ float g_s[BATCH*HID];        // SE gate
__device__ float g_sc1[HID], g_sh1[HID];
__device__ float g_sc2[HID], g_sh2[HID];
__device__ float g_sc3[COUT], g_sh3[COUT];

__device__ __forceinline__ float silu_f(float v)    { return v / (1.f + __expf(-v)); }
__device__ __forceinline__ float sigmoid_f(float v) { return 1.f / (1.f + __expf(-v)); }

__device__ __forceinline__ uint32_t smem_u32(const void* p) {
    uint32_t a;
    asm("{ .reg .u64 t; cvta.to.shared.u64 t, %1; cvt.u32.u64 %0, t; }" : "=r"(a) : "l"(p));
    return a;
}
__device__ __forceinline__ void cp_async4(uint32_t dst, const void* src, int szbytes) {
    asm volatile("cp.async.ca.shared.global [%0], [%1], 4, %2;"
                 :: "r"(dst), "l"(src), "r"(szbytes) : "memory");
}
__device__ __forceinline__ void cp_async16(uint32_t dst, const void* src) {
    asm volatile("cp.async.cg.shared.global [%0], [%1], 16;"
                 :: "r"(dst), "l"(src) : "memory");
}
#define CP_COMMIT()  asm volatile("cp.async.commit_group;" ::: "memory")
#define CP_WAIT(n)   asm volatile("cp.async.wait_group %0;" :: "n"(n) : "memory")

// mma.sync m16n8k8 tf32 (inputs = raw fp32 bits; HW uses top tf32 bits)
__device__ __forceinline__ void mma_tf32(float* c, const uint32_t* a, const uint32_t* b) {
    asm volatile(
        "mma.sync.aligned.m16n8k8.row.col.f32.tf32.tf32.f32 "
        "{%0,%1,%2,%3}, {%4,%5,%6,%7}, {%8,%9}, {%0,%1,%2,%3};"
        : "+f"(c[0]), "+f"(c[1]), "+f"(c[2]), "+f"(c[3])
        : "r"(a[0]), "r"(a[1]), "r"(a[2]), "r"(a[3]), "r"(b[0]), "r"(b[1]));
}

// ---------------------------------------------------------------------------
// Kernel 0: fold BN params into per-channel scale/shift
// ---------------------------------------------------------------------------
__global__ void bn_prep_kernel(
    const float* __restrict__ g1, const float* __restrict__ b1,
    const float* __restrict__ m1, const float* __restrict__ v1,
    const float* __restrict__ g2, const float* __restrict__ b2,
    const float* __restrict__ m2, const float* __restrict__ v2,
    const float* __restrict__ g3, const float* __restrict__ b3,
    const float* __restrict__ m3, const float* __restrict__ v3)
{
    int t = threadIdx.x;
    if (t < HID) {
        float s1 = g1[t] * rsqrtf(v1[t] + 1e-5f);
        g_sc1[t] = s1; g_sh1[t] = b1[t] - m1[t] * s1;
        float s2 = g2[t] * rsqrtf(v2[t] + 1e-5f);
        g_sc2[t] = s2; g_sh2[t] = b2[t] - m2[t] * s2;
    }
    if (t < COUT) {
        float s3 = g3[t] * rsqrtf(v3[t] + 1e-5f);
        g_sc3[t] = s3; g_sh3[t] = b3[t] - m3[t] * s3;
    }
}

// ---------------------------------------------------------------------------
// Kernel 1: expand conv 3x3 (64->384), mma.sync tf32, cp.async double-buffer.
//   GEMM: C[384, 100352] = W[384, 576] @ im2col(x)[576, 100352]
//   Block M=128 x N=128, 8 warps (4m x 2n), warp tile 32x64.
//   K-chunk 16 (36 iterations), 2 smem buffers.
//   As: [m][k] pad 20 (banks (g*20+t)%32 all distinct in a warp).
//   Bs: [k][n] pad 136 (banks (8t+g)%32 all distinct).
// ---------------------------------------------------------------------------
#define EXP_KC 16
#define EXP_NC (KEXP / EXP_KC)     // 36
#define PADA 20
#define PADB 136

__global__ __launch_bounds__(256, 2)
void expand_conv_mma_kernel(const float* __restrict__ x, const float* __restrict__ w)
{
    __shared__ float As[2][128][PADA];
    __shared__ float Bs[2][EXP_KC][PADB];

    const int tid = threadIdx.x;
    const int wid = tid >> 5, lid = tid & 31;
    const int g = lid >> 2, t = lid & 3;
    const int wm = (wid >> 1) * 32, wn = (wid & 1) * 64;
    const int m0 = blockIdx.y * 128, n0 = blockIdx.x * 128;

    // --- A loader: thread -> (row am, 8 k's) ---
    const int am = tid >> 1;
    const int ah = (tid & 1) * 8;
    const float* wsrc = w + (size_t)(m0 + am) * KEXP + ah;
    const uint32_t adst[2] = { smem_u32(&As[0][am][ah]), smem_u32(&As[1][am][ah]) };

    // --- B loader: thread -> (k-row kk 0..15, 8 consecutive n) ---
    const int kk = tid >> 4;
    const int n8 = (tid & 15) * 8;
    const uint32_t bdst[2] = { smem_u32(&Bs[0][kk][n8]), smem_u32(&Bs[1][kk][n8]) };
    int xoff[8], boh[8], bow[8];
#pragma unroll
    for (int j = 0; j < 8; j++) {
        int ncol = n0 + n8 + j;
        int b = ncol / HW;
        int p = ncol - b * HW;
        int oh = p / HS;
        int ow = p - oh * HS;
        boh[j] = oh; bow[j] = ow;
        xoff[j] = b * (CIN * HW) + oh * HS + ow;
    }

    auto issue = [&](int c, int buf) {
        // A: 16 floats per row chunk, this thread's 8 = 2 x 16B
        const float* s = wsrc + c * EXP_KC;
        cp_async16(adst[buf], s);
        cp_async16(adst[buf] + 16, s + 4);
        // B: im2col gather, 8 x 4B with zfill predicate
        int kq = c * EXP_KC + kk;
        int ic = kq / 9;
        int r  = kq - ic * 9;
        int r3 = r / 3;
        int dh = r3 - 1;
        int dw = (r - r3 * 3) - 1;
        const float* xp = x + (size_t)ic * HW + dh * HS + dw;
#pragma unroll
        for (int j = 0; j < 8; j++) {
            int ih = boh[j] + dh;
            int iw = bow[j] + dw;
            bool ok = ((unsigned)ih < (unsigned)HS) && ((unsigned)iw < (unsigned)HS);
            const float* src = ok ? (xp + xoff[j]) : x;
            cp_async4(bdst[buf] + j * 4, src, ok ? 4 : 0);
        }
    };

    float acc[2][8][4];
#pragma unroll
    for (int i = 0; i < 2; i++)
#pragma unroll
        for (int j = 0; j < 8; j++)
#pragma unroll
            for (int q = 0; q < 4; q++) acc[i][j][q] = 0.f;

    issue(0, 0);
    CP_COMMIT();

    for (int c = 0; c < EXP_NC; c++) {
        const int cur = c & 1;
        if (c + 1 < EXP_NC) {
            issue(c + 1, cur ^ 1);
            CP_COMMIT();
            CP_WAIT(1);
        } else {
            CP_WAIT(0);
        }
        __syncthreads();

#pragma unroll
        for (int s = 0; s < 2; s++) {
            uint32_t afr[2][4];
#pragma unroll
            for (int fm = 0; fm < 2; fm++) {
                int mb = wm + fm * 16;
                afr[fm][0] = __float_as_uint(As[cur][mb + g][8 * s + t]);
                afr[fm][1] = __float_as_uint(As[cur][mb + g + 8][8 * s + t]);
                afr[fm][2] = __float_as_uint(As[cur][mb + g][8 * s + t + 4]);
                afr[fm][3] = __float_as_uint(As[cur][mb + g + 8][8 * s + t + 4]);
            }
#pragma unroll
            for (int fn = 0; fn < 8; fn++) {
                uint32_t bfr[2];
                int nb = wn + fn * 8;
                bfr[0] = __float_as_uint(Bs[cur][8 * s + t][nb + g]);
                bfr[1] = __float_as_uint(Bs[cur][8 * s + t + 4][nb + g]);
                mma_tf32(acc[0][fn], afr[0], bfr);
                mma_tf32(acc[1][fn], afr[1], bfr);
            }
        }
        __syncthreads();
    }

    // --- epilogue: BN1 + SiLU, write NCHW h (proven in round 7) ---
#pragma unroll
    for (int fm = 0; fm < 2; fm++) {
#pragma unroll
        for (int half = 0; half < 2; half++) {
            int oc = m0 + wm + fm * 16 + g + half * 8;
            float sc = g_sc1[oc], sh = g_sh1[oc];
#pragma unroll
            for (int fn = 0; fn < 8; fn++) {
#pragma unroll
                for (int e = 0; e < 2; e++) {
                    int ncol = n0 + wn + fn * 8 + 2 * t + e;
                    int b = ncol / HW;
                    int p = ncol - b * HW;
                    float v = fmaf(acc[fm][fn][half * 2 + e], sc, sh);
                    g_h[((size_t)b * HID + oc) * HW + p] = silu_f(v);
                }
            }
        }
    }
}

// ---------------------------------------------------------------------------
// Kernel 2: depthwise 3x3 + BN2 + SiLU, fused global-average-pool partial
// ---------------------------------------------------------------------------
__global__ __launch_bounds__(256)
void dw_conv_kernel(const float* __restrict__ wdw)
{
    const int bc = blockIdx.x;            // b*HID + c
    const int c  = bc % HID;
    const float* __restrict__ hp = g_h + (size_t)bc * HW;
    float* __restrict__ dp = g_d + (size_t)bc * HW;

    float w[9];
#pragma unroll
    for (int i = 0; i < 9; i++) w[i] = wdw[c * 9 + i];
    const float sc = g_sc2[c], sh = g_sh2[c];

    float lsum = 0.f;
    for (int p = threadIdx.x; p < HW; p += 256) {
        int oh = p / HS;
        int ow = p - oh * HS;
        float acc = 0.f;
#pragma unroll
        for (int kh = 0; kh < 3; kh++) {
            int ih = oh + kh - 1;
            if ((unsigned)ih < (unsigned)HS) {
#pragma unroll
                for (int kw = 0; kw < 3; kw++) {
                    int iw = ow + kw - 1;
                    if ((unsigned)iw < (unsigned)HS)
                        acc = fmaf(w[kh * 3 + kw], hp[ih * HS + iw], acc);
                }
            }
        }
        float v = silu_f(fmaf(acc, sc, sh));
        dp[p] = v;
        lsum += v;
    }

    __shared__ float red[256];
    red[threadIdx.x] = lsum;
    __syncthreads();
#pragma unroll
    for (int s = 128; s > 0; s >>= 1) {
        if (threadIdx.x < s) red[threadIdx.x] += red[threadIdx.x + s];
        __syncthreads();
    }
    if (threadIdx.x == 0) g_pool[bc] = red[0] * (1.f / (float)HW);
}

// ---------------------------------------------------------------------------
// Kernel 3: squeeze-excitation (warp-parallel first FC; measured 9.4us)
// ---------------------------------------------------------------------------
__global__ void se_kernel(const float* __restrict__ w1, const float* __restrict__ w2)
{
    const int b = blockIdx.x;
    const int t = threadIdx.x;            // 0..383
    const int wid = t >> 5;               // 0..11
    const int lid = t & 31;
    __shared__ float pool[HID];
    __shared__ float s1[RED];

    pool[t] = g_pool[b * HID + t];
    __syncthreads();

    for (int r = wid; r < RED; r += 12) {
        const float* wr = w1 + r * HID;
        float part = 0.f;
#pragma unroll
        for (int c = lid; c < HID; c += 32)
            part = fmaf(wr[c], pool[c], part);
#pragma unroll
        for (int off = 16; off > 0; off >>= 1)
            part += __shfl_xor_sync(0xFFFFFFFF, part, off);
        if (lid == 0) s1[r] = silu_f(part);
    }
    __syncthreads();

    float acc = 0.f;
#pragma unroll
    for (int r = 0; r < RED; r++)
        acc = fmaf(w2[t * RED + r], s1[r], acc);
    g_s[b * HID + t] = sigmoid_f(acc);
}

// ---------------------------------------------------------------------------
// Kernel 4: pointwise 1x1 (384->64), mma.sync tf32, cp.async double-buffer.
//   BN=64 pixel tile (64 | 3136 => block within one batch => SE gate folds
//   into A). Block M=64 x N=64, 8 warps (2m x 4n), warp tile 32x16.
//   K-chunk 16 (24 iterations). B loads are clean 16B cp.async from g_d.
// ---------------------------------------------------------------------------
#define PW_KC 16
#define PW_NC (HID / PW_KC)      // 24
#define PWPB 72

__global__ __launch_bounds__(256, 3)
void pw_conv_mma_kernel(const float* __restrict__ wpw, const float* __restrict__ x,
                        float* __restrict__ out)
{
    __shared__ float As[2][64][PADA];    // [m][k], gate-scaled weights
    __shared__ float Bs[2][PW_KC][PWPB]; // [k][n]

    const int tid = threadIdx.x;
    const int wid = tid >> 5, lid = tid & 31;
    const int g = lid >> 2, t = lid & 3;
    const int wm = (wid & 1) * 32;       // 0 or 32
    const int wn = (wid >> 1) * 16;      // 0,16,32,48
    const int n0 = blockIdx.x * 64;
    const int b  = n0 / HW;              // constant: 64 divides 3136
    const int p0 = n0 - b * HW;

    // --- A loader: thread -> (row am 0..63, 4 k's); gate folded on commit ---
    const int am  = tid >> 2;
    const int ak4 = (tid & 3) * 4;
    const float* wrow = wpw + (size_t)am * HID + ak4;
    const float* srow = g_s + (size_t)b * HID + ak4;
    float4 wv, sv;
    auto fetchA = [&](int c) {
        wv = *reinterpret_cast<const float4*>(wrow + c * PW_KC);
        sv = *reinterpret_cast<const float4*>(srow + c * PW_KC);
    };
    auto commitA = [&](int buf) {
        As[buf][am][ak4 + 0] = wv.x * sv.x;
        As[buf][am][ak4 + 1] = wv.y * sv.y;
        As[buf][am][ak4 + 2] = wv.z * sv.z;
        As[buf][am][ak4 + 3] = wv.w * sv.w;
    };

    // --- B loader: thread -> (k-row kk 0..15, 4 consecutive n = 16B) ---
    const int kk = tid >> 4;
    const int n4 = (tid & 15) * 4;
    const uint32_t bdst[2] = { smem_u32(&Bs[0][kk][n4]), smem_u32(&Bs[1][kk][n4]) };
    const float* bsrc0 = g_d + ((size_t)b * HID + kk) * HW + p0 + n4;
    auto issueB = [&](int c, int buf) {
        cp_async16(bdst[buf], bsrc0 + (size_t)(c * PW_KC) * HW);
    };

    float acc[2][2][4];
#pragma unroll
    for (int i = 0; i < 2; i++)
#pragma unroll
        for (int j = 0; j < 2; j++)
#pragma unroll
            for (int q = 0; q < 4; q++) acc[i][j][q] = 0.f;

    fetchA(0);
    issueB(0, 0);
    CP_COMMIT();

    for (int c = 0; c < PW_NC; c++) {
        const int cur = c & 1;
        commitA(cur);
        if (c + 1 < PW_NC) {
            issueB(c + 1, cur ^ 1);
            CP_COMMIT();
            CP_WAIT(1);
        } else {
            CP_WAIT(0);
        }
        __syncthreads();
        if (c + 1 < PW_NC) fetchA(c + 1);   // overlap LDG with mma

#pragma unroll
        for (int s = 0; s < 2; s++) {
            uint32_t afr[2][4];
#pragma unroll
            for (int fm = 0; fm < 2; fm++) {
                int mb = wm + fm * 16;
                afr[fm][0] = __float_as_uint(As[cur][mb + g][8 * s + t]);
                afr[fm][1] = __float_as_uint(As[cur][mb + g + 8][8 * s + t]);
                afr[fm][2] = __float_as_uint(As[cur][mb + g][8 * s + t + 4]);
                afr[fm][3] = __float_as_uint(As[cur][mb + g + 8][8 * s + t + 4]);
            }
#pragma unroll
            for (int fn = 0; fn < 2; fn++) {
                uint32_t bfr[2];
                int nb = wn + fn * 8;
                bfr[0] = __float_as_uint(Bs[cur][8 * s + t][nb + g]);
                bfr[1] = __float_as_uint(Bs[cur][8 * s + t + 4][nb + g]);
                mma_tf32(acc[0][fn], afr[0], bfr);
                mma_tf32(acc[1][fn], afr[1], bfr);
            }
        }
        __syncthreads();
    }

    // --- epilogue: BN3 + residual add ---
#pragma unroll
    for (int fm = 0; fm < 2; fm++) {
#pragma unroll
        for (int half = 0; half < 2; half++) {
            int oc = wm + fm * 16 + g + half * 8;
            float sc = g_sc3[oc], sh = g_sh3[oc];
#pragma unroll
            for (int fn = 0; fn < 2; fn++) {
#pragma unroll
                for (int e = 0; e < 2; e++) {
                    int p = p0 + wn + fn * 8 + 2 * t + e;
                    int idx = (b * COUT + oc) * HW + p;
                    out[idx] = fmaf(acc[fm][fn][half * 2 + e], sc, sh) + x[idx];
                }
            }
        }
    }
}

// ---------------------------------------------------------------------------
// Launch
// ---------------------------------------------------------------------------
extern "C" void kernel_launch(void* const* d_in, const int* in_sizes, int n_in,
                              void* d_out, int out_size)
{
    const float* x     = (const float*)d_in[0];
    const float* w_exp = (const float*)d_in[1];
    const float* g1 = (const float*)d_in[2];
    const float* b1 = (const float*)d_in[3];
    const float* m1 = (const float*)d_in[4];
    const float* v1 = (const float*)d_in[5];
    const float* w_dw = (const float*)d_in[6];
    const float* g2 = (const float*)d_in[7];
    const float* b2 = (const float*)d_in[8];
    const float* m2 = (const float*)d_in[9];
    const float* v2 = (const float*)d_in[10];
    const float* w_se1 = (const float*)d_in[11];
    const float* w_se2 = (const float*)d_in[12];
    const float* w_pw  = (const float*)d_in[13];
    const float* g3 = (const float*)d_in[14];
    const float* b3 = (const float*)d_in[15];
    const float* m3 = (const float*)d_in[16];
    const float* v3 = (const float*)d_in[17];
    float* out = (float*)d_out;

    bn_prep_kernel<<<1, HID>>>(g1, b1, m1, v1, g2, b2, m2, v2, g3, b3, m3, v3);
    expand_conv_mma_kernel<<<dim3(NPIX / 128, HID / 128), 256>>>(x, w_exp);
    dw_conv_kernel<<<BATCH * HID, 256>>>(w_dw);
    se_kernel<<<BATCH, HID>>>(w_se1, w_se2);
    pw_conv_mma_kernel<<<NPIX / 64, 256>>>(w_pw, x, out);
}

// round 12
// speedup vs baseline: 1.5921x; 1.0604x over previous
#include <cuda_runtime.h>
#include <cuda_fp16.h>
#include <cstdint>

// Problem constants
#define BATCH 32
#define CIN   64
#define HID   384
#define RED   16
#define COUT  64
#define HS    56
#define HW    3136              // 56*56
#define NPIX  (BATCH*HW)        // 100352
#define KEXP  (CIN*9)           // 576

// Scratch (allocation-free: __device__ globals)
__device__ float g_h[BATCH*HID*HW];     // after expand conv + BN + SiLU
__device__ float g_d[BATCH*HID*HW];     // after depthwise + BN + SiLU
__device__ float g_pool[BATCH*HID];     // global average pool of g_d
__device__ float g_s[BATCH*HID];        // SE gate
__device__ float g_sc1[HID], g_sh1[HID];
__device__ float g_sc2[HID], g_sh2[HID];
__device__ float g_sc3[COUT], g_sh3[COUT];

__device__ __forceinline__ float silu_f(float v)    { return v / (1.f + __expf(-v)); }
__device__ __forceinline__ float sigmoid_f(float v) { return 1.f / (1.f + __expf(-v)); }

__device__ __forceinline__ uint32_t smem_u32(const void* p) {
    uint32_t a;
    asm("{ .reg .u64 t; cvta.to.shared.u64 t, %1; cvt.u32.u64 %0, t; }" : "=r"(a) : "l"(p));
    return a;
}
__device__ __forceinline__ void cp_async4(uint32_t dst, const void* src, int szbytes) {
    asm volatile("cp.async.ca.shared.global [%0], [%1], 4, %2;"
                 :: "r"(dst), "l"(src), "r"(szbytes) : "memory");
}
__device__ __forceinline__ void cp_async16(uint32_t dst, const void* src) {
    asm volatile("cp.async.cg.shared.global [%0], [%1], 16;"
                 :: "r"(dst), "l"(src) : "memory");
}
#define CP_COMMIT()  asm volatile("cp.async.commit_group;" ::: "memory")
#define CP_WAIT(n)   asm volatile("cp.async.wait_group %0;" :: "n"(n) : "memory")

// pack two fp32 -> half2 register (x=lo, y=hi)
__device__ __forceinline__ uint32_t pack_h2(float lo, float hi) {
    __half2 h = __float22half2_rn(make_float2(lo, hi));
    return *reinterpret_cast<uint32_t*>(&h);
}
__device__ __forceinline__ uint32_t pack_h2v(float2 v) { return pack_h2(v.x, v.y); }

// mma.sync m16n8k16 fp16 with fp32 accumulate
__device__ __forceinline__ void mma_f16(float* c, const uint32_t* a, const uint32_t* b) {
    asm volatile(
        "mma.sync.aligned.m16n8k16.row.col.f32.f16.f16.f32 "
        "{%0,%1,%2,%3}, {%4,%5,%6,%7}, {%8,%9}, {%0,%1,%2,%3};"
        : "+f"(c[0]), "+f"(c[1]), "+f"(c[2]), "+f"(c[3])
        : "r"(a[0]), "r"(a[1]), "r"(a[2]), "r"(a[3]), "r"(b[0]), "r"(b[1]));
}

// ---------------------------------------------------------------------------
// Kernel 0: fold BN params into per-channel scale/shift
// ---------------------------------------------------------------------------
__global__ void bn_prep_kernel(
    const float* __restrict__ g1, const float* __restrict__ b1,
    const float* __restrict__ m1, const float* __restrict__ v1,
    const float* __restrict__ g2, const float* __restrict__ b2,
    const float* __restrict__ m2, const float* __restrict__ v2,
    const float* __restrict__ g3, const float* __restrict__ b3,
    const float* __restrict__ m3, const float* __restrict__ v3)
{
    int t = threadIdx.x;
    if (t < HID) {
        float s1 = g1[t] * rsqrtf(v1[t] + 1e-5f);
        g_sc1[t] = s1; g_sh1[t] = b1[t] - m1[t] * s1;
        float s2 = g2[t] * rsqrtf(v2[t] + 1e-5f);
        g_sc2[t] = s2; g_sh2[t] = b2[t] - m2[t] * s2;
    }
    if (t < COUT) {
        float s3 = g3[t] * rsqrtf(v3[t] + 1e-5f);
        g_sc3[t] = s3; g_sh3[t] = b3[t] - m3[t] * s3;
    }
}

// ---------------------------------------------------------------------------
// Kernel 1: expand conv 3x3 (64->384), mma.sync fp16 (f32 accum),
//           cp.async double-buffer. Block M=128 x N=128, 8 warps (4m x 2n),
//           warp tile 32x64, K-chunk 16 (36 iterations).
//   As: [m][k] fp32, pad 20. Bs: [k][n] fp32, pad 132
//   (B k-pair LDS banks (264t+g)%32 bijective -> conflict-free).
// ---------------------------------------------------------------------------
#define EXP_KC 16
#define EXP_NC (KEXP / EXP_KC)     // 36
#define PADA 20
#define PADB 132

__global__ __launch_bounds__(256, 2)
void expand_conv_mma_kernel(const float* __restrict__ x, const float* __restrict__ w)
{
    __shared__ float As[2][128][PADA];
    __shared__ float Bs[2][EXP_KC][PADB];

    const int tid = threadIdx.x;
    const int wid = tid >> 5, lid = tid & 31;
    const int g = lid >> 2, t = lid & 3;
    const int wm = (wid >> 1) * 32, wn = (wid & 1) * 64;
    const int m0 = blockIdx.y * 128, n0 = blockIdx.x * 128;

    // --- A loader: thread -> (row am, 8 k's) ---
    const int am = tid >> 1;
    const int ah = (tid & 1) * 8;
    const float* wsrc = w + (size_t)(m0 + am) * KEXP + ah;
    const uint32_t adst[2] = { smem_u32(&As[0][am][ah]), smem_u32(&As[1][am][ah]) };

    // --- B loader: thread -> (k-row kk 0..15, 8 consecutive n) ---
    const int kk = tid >> 4;
    const int n8 = (tid & 15) * 8;
    const uint32_t bdst[2] = { smem_u32(&Bs[0][kk][n8]), smem_u32(&Bs[1][kk][n8]) };
    int xoff[8], boh[8], bow[8];
#pragma unroll
    for (int j = 0; j < 8; j++) {
        int ncol = n0 + n8 + j;
        int b = ncol / HW;
        int p = ncol - b * HW;
        int oh = p / HS;
        int ow = p - oh * HS;
        boh[j] = oh; bow[j] = ow;
        xoff[j] = b * (CIN * HW) + oh * HS + ow;
    }

    auto issue = [&](int c, int buf) {
        const float* s = wsrc + c * EXP_KC;
        cp_async16(adst[buf], s);
        cp_async16(adst[buf] + 16, s + 4);
        int kq = c * EXP_KC + kk;
        int ic = kq / 9;
        int r  = kq - ic * 9;
        int r3 = r / 3;
        int dh = r3 - 1;
        int dw = (r - r3 * 3) - 1;
        const float* xp = x + (size_t)ic * HW + dh * HS + dw;
#pragma unroll
        for (int j = 0; j < 8; j++) {
            int ih = boh[j] + dh;
            int iw = bow[j] + dw;
            bool ok = ((unsigned)ih < (unsigned)HS) && ((unsigned)iw < (unsigned)HS);
            const float* src = ok ? (xp + xoff[j]) : x;
            cp_async4(bdst[buf] + j * 4, src, ok ? 4 : 0);
        }
    };

    float acc[2][8][4];
#pragma unroll
    for (int i = 0; i < 2; i++)
#pragma unroll
        for (int j = 0; j < 8; j++)
#pragma unroll
            for (int q = 0; q < 4; q++) acc[i][j][q] = 0.f;

    issue(0, 0);
    CP_COMMIT();

    for (int c = 0; c < EXP_NC; c++) {
        const int cur = c & 1;
        if (c + 1 < EXP_NC) {
            issue(c + 1, cur ^ 1);
            CP_COMMIT();
            CP_WAIT(1);
        } else {
            CP_WAIT(0);
        }
        __syncthreads();

        // --- fp16 fragments over full k16 chunk ---
        uint32_t afr[2][4];
#pragma unroll
        for (int fm = 0; fm < 2; fm++) {
            int mb = wm + fm * 16;
            afr[fm][0] = pack_h2v(*reinterpret_cast<const float2*>(&As[cur][mb + g][2 * t]));
            afr[fm][1] = pack_h2v(*reinterpret_cast<const float2*>(&As[cur][mb + g + 8][2 * t]));
            afr[fm][2] = pack_h2v(*reinterpret_cast<const float2*>(&As[cur][mb + g][2 * t + 8]));
            afr[fm][3] = pack_h2v(*reinterpret_cast<const float2*>(&As[cur][mb + g + 8][2 * t + 8]));
        }
#pragma unroll
        for (int fn = 0; fn < 8; fn++) {
            int nb = wn + fn * 8;
            uint32_t bfr[2];
            bfr[0] = pack_h2(Bs[cur][2 * t][nb + g],     Bs[cur][2 * t + 1][nb + g]);
            bfr[1] = pack_h2(Bs[cur][2 * t + 8][nb + g], Bs[cur][2 * t + 9][nb + g]);
            mma_f16(acc[0][fn], afr[0], bfr);
            mma_f16(acc[1][fn], afr[1], bfr);
        }
        __syncthreads();
    }

    // --- epilogue: BN1 + SiLU, write NCHW h (C layout identical to tf32) ---
#pragma unroll
    for (int fm = 0; fm < 2; fm++) {
#pragma unroll
        for (int half = 0; half < 2; half++) {
            int oc = m0 + wm + fm * 16 + g + half * 8;
            float sc = g_sc1[oc], sh = g_sh1[oc];
#pragma unroll
            for (int fn = 0; fn < 8; fn++) {
#pragma unroll
                for (int e = 0; e < 2; e++) {
                    int ncol = n0 + wn + fn * 8 + 2 * t + e;
                    int b = ncol / HW;
                    int p = ncol - b * HW;
                    float v = fmaf(acc[fm][fn][half * 2 + e], sc, sh);
                    g_h[((size_t)b * HID + oc) * HW + p] = silu_f(v);
                }
            }
        }
    }
}

// ---------------------------------------------------------------------------
// Kernel 2: depthwise 3x3 + BN2 + SiLU, fused global-average-pool partial
// ---------------------------------------------------------------------------
__global__ __launch_bounds__(256)
void dw_conv_kernel(const float* __restrict__ wdw)
{
    const int bc = blockIdx.x;            // b*HID + c
    const int c  = bc % HID;
    const float* __restrict__ hp = g_h + (size_t)bc * HW;
    float* __restrict__ dp = g_d + (size_t)bc * HW;

    float w[9];
#pragma unroll
    for (int i = 0; i < 9; i++) w[i] = wdw[c * 9 + i];
    const float sc = g_sc2[c], sh = g_sh2[c];

    float lsum = 0.f;
    for (int p = threadIdx.x; p < HW; p += 256) {
        int oh = p / HS;
        int ow = p - oh * HS;
        float acc = 0.f;
#pragma unroll
        for (int kh = 0; kh < 3; kh++) {
            int ih = oh + kh - 1;
            if ((unsigned)ih < (unsigned)HS) {
#pragma unroll
                for (int kw = 0; kw < 3; kw++) {
                    int iw = ow + kw - 1;
                    if ((unsigned)iw < (unsigned)HS)
                        acc = fmaf(w[kh * 3 + kw], hp[ih * HS + iw], acc);
                }
            }
        }
        float v = silu_f(fmaf(acc, sc, sh));
        dp[p] = v;
        lsum += v;
    }

    __shared__ float red[256];
    red[threadIdx.x] = lsum;
    __syncthreads();
#pragma unroll
    for (int s = 128; s > 0; s >>= 1) {
        if (threadIdx.x < s) red[threadIdx.x] += red[threadIdx.x + s];
        __syncthreads();
    }
    if (threadIdx.x == 0) g_pool[bc] = red[0] * (1.f / (float)HW);
}

// ---------------------------------------------------------------------------
// Kernel 3: squeeze-excitation (warp-parallel first FC; measured 7.6us)
// ---------------------------------------------------------------------------
__global__ void se_kernel(const float* __restrict__ w1, const float* __restrict__ w2)
{
    const int b = blockIdx.x;
    const int t = threadIdx.x;            // 0..383
    const int wid = t >> 5;               // 0..11
    const int lid = t & 31;
    __shared__ float pool[HID];
    __shared__ float s1[RED];

    pool[t] = g_pool[b * HID + t];
    __syncthreads();

    for (int r = wid; r < RED; r += 12) {
        const float* wr = w1 + r * HID;
        float part = 0.f;
#pragma unroll
        for (int c = lid; c < HID; c += 32)
            part = fmaf(wr[c], pool[c], part);
#pragma unroll
        for (int off = 16; off > 0; off >>= 1)
            part += __shfl_xor_sync(0xFFFFFFFF, part, off);
        if (lid == 0) s1[r] = silu_f(part);
    }
    __syncthreads();

    float acc = 0.f;
#pragma unroll
    for (int r = 0; r < RED; r++)
        acc = fmaf(w2[t * RED + r], s1[r], acc);
    g_s[b * HID + t] = sigmoid_f(acc);
}

// ---------------------------------------------------------------------------
// Kernel 4: pointwise 1x1 (384->64), mma.sync fp16, cp.async double-buffer.
//   BN=64 pixel tile (block in one batch => SE gate folds into A).
//   Block M=64 x N=64, 8 warps (2m x 4n), K-chunk 16 (24 iterations).
//   Bs pad 68 (k-pair LDS banks (136t+g)%32 = (8t+g) distinct).
// ---------------------------------------------------------------------------
#define PW_KC 16
#define PW_NC (HID / PW_KC)      // 24
#define PWPB 68

__global__ __launch_bounds__(256, 3)
void pw_conv_mma_kernel(const float* __restrict__ wpw, const float* __restrict__ x,
                        float* __restrict__ out)
{
    __shared__ float As[2][64][PADA];    // [m][k], gate-scaled weights
    __shared__ float Bs[2][PW_KC][PWPB]; // [k][n]

    const int tid = threadIdx.x;
    const int wid = tid >> 5, lid = tid & 31;
    const int g = lid >> 2, t = lid & 3;
    const int wm = (wid & 1) * 32;
    const int wn = (wid >> 1) * 16;
    const int n0 = blockIdx.x * 64;
    const int b  = n0 / HW;
    const int p0 = n0 - b * HW;

    // --- A loader: thread -> (row am 0..63, 4 k's); gate folded on commit ---
    const int am  = tid >> 2;
    const int ak4 = (tid & 3) * 4;
    const float* wrow = wpw + (size_t)am * HID + ak4;
    const float* srow = g_s + (size_t)b * HID + ak4;
    float4 wv, sv;
    auto fetchA = [&](int c) {
        wv = *reinterpret_cast<const float4*>(wrow + c * PW_KC);
        sv = *reinterpret_cast<const float4*>(srow + c * PW_KC);
    };
    auto commitA = [&](int buf) {
        As[buf][am][ak4 + 0] = wv.x * sv.x;
        As[buf][am][ak4 + 1] = wv.y * sv.y;
        As[buf][am][ak4 + 2] = wv.z * sv.z;
        As[buf][am][ak4 + 3] = wv.w * sv.w;
    };

    // --- B loader: thread -> (k-row kk 0..15, 4 consecutive n = 16B) ---
    const int kk = tid >> 4;
    const int n4 = (tid & 15) * 4;
    const uint32_t bdst[2] = { smem_u32(&Bs[0][kk][n4]), smem_u32(&Bs[1][kk][n4]) };
    const float* bsrc0 = g_d + ((size_t)b * HID + kk) * HW + p0 + n4;
    auto issueB = [&](int c, int buf) {
        cp_async16(bdst[buf], bsrc0 + (size_t)(c * PW_KC) * HW);
    };

    float acc[2][2][4];
#pragma unroll
    for (int i = 0; i < 2; i++)
#pragma unroll
        for (int j = 0; j < 2; j++)
#pragma unroll
            for (int q = 0; q < 4; q++) acc[i][j][q] = 0.f;

    fetchA(0);
    issueB(0, 0);
    CP_COMMIT();

    for (int c = 0; c < PW_NC; c++) {
        const int cur = c & 1;
        commitA(cur);
        if (c + 1 < PW_NC) {
            issueB(c + 1, cur ^ 1);
            CP_COMMIT();
            CP_WAIT(1);
        } else {
            CP_WAIT(0);
        }
        __syncthreads();
        if (c + 1 < PW_NC) fetchA(c + 1);   // overlap LDG with mma

        uint32_t afr[2][4];
#pragma unroll
        for (int fm = 0; fm < 2; fm++) {
            int mb = wm + fm * 16;
            afr[fm][0] = pack_h2v(*reinterpret_cast<const float2*>(&As[cur][mb + g][2 * t]));
            afr[fm][1] = pack_h2v(*reinterpret_cast<const float2*>(&As[cur][mb + g + 8][2 * t]));
            afr[fm][2] = pack_h2v(*reinterpret_cast<const float2*>(&As[cur][mb + g][2 * t + 8]));
            afr[fm][3] = pack_h2v(*reinterpret_cast<const float2*>(&As[cur][mb + g + 8][2 * t + 8]));
        }
#pragma unroll
        for (int fn = 0; fn < 2; fn++) {
            int nb = wn + fn * 8;
            uint32_t bfr[2];
            bfr[0] = pack_h2(Bs[cur][2 * t][nb + g],     Bs[cur][2 * t + 1][nb + g]);
            bfr[1] = pack_h2(Bs[cur][2 * t + 8][nb + g], Bs[cur][2 * t + 9][nb + g]);
            mma_f16(acc[0][fn], afr[0], bfr);
            mma_f16(acc[1][fn], afr[1], bfr);
        }
        __syncthreads();
    }

    // --- epilogue: BN3 + residual add ---
#pragma unroll
    for (int fm = 0; fm < 2; fm++) {
#pragma unroll
        for (int half = 0; half < 2; half++) {
            int oc = wm + fm * 16 + g + half * 8;
            float sc = g_sc3[oc], sh = g_sh3[oc];
#pragma unroll
            for (int fn = 0; fn < 2; fn++) {
#pragma unroll
                for (int e = 0; e < 2; e++) {
                    int p = p0 + wn + fn * 8 + 2 * t + e;
                    int idx = (b * COUT + oc) * HW + p;
                    out[idx] = fmaf(acc[fm][fn][half * 2 + e], sc, sh) + x[idx];
                }
            }
        }
    }
}

// ---------------------------------------------------------------------------
// Launch
// ---------------------------------------------------------------------------
extern "C" void kernel_launch(void* const* d_in, const int* in_sizes, int n_in,
                              void* d_out, int out_size)
{
    const float* x     = (const float*)d_in[0];
    const float* w_exp = (const float*)d_in[1];
    const float* g1 = (const float*)d_in[2];
    const float* b1 = (const float*)d_in[3];
    const float* m1 = (const float*)d_in[4];
    const float* v1 = (const float*)d_in[5];
    const float* w_dw = (const float*)d_in[6];
    const float* g2 = (const float*)d_in[7];
    const float* b2 = (const float*)d_in[8];
    const float* m2 = (const float*)d_in[9];
    const float* v2 = (const float*)d_in[10];
    const float* w_se1 = (const float*)d_in[11];
    const float* w_se2 = (const float*)d_in[12];
    const float* w_pw  = (const float*)d_in[13];
    const float* g3 = (const float*)d_in[14];
    const float* b3 = (const float*)d_in[15];
    const float* m3 = (const float*)d_in[16];
    const float* v3 = (const float*)d_in[17];
    float* out = (float*)d_out;

    bn_prep_kernel<<<1, HID>>>(g1, b1, m1, v1, g2, b2, m2, v2, g3, b3, m3, v3);
    expand_conv_mma_kernel<<<dim3(NPIX / 128, HID / 128), 256>>>(x, w_exp);
    dw_conv_kernel<<<BATCH * HID, 256>>>(w_dw);
    se_kernel<<<BATCH, HID>>>(w_se1, w_se2);
    pw_conv_mma_kernel<<<NPIX / 64, 256>>>(w_pw, x, out);
}